// round 10
// baseline (speedup 1.0000x reference)
#include <cuda_runtime.h>
#include <cuda.h>
#include <cuda_fp16.h>
#include <cstdint>

// ============================================================================
// Problem constants   (R4/R9-passing shape: 256x128, 8x 64x64 warps, 288 thr)
// ============================================================================
#define DIN    4096
#define DOUT   12288
#define MROWS  4096

#define BM     256
#define BN     128
#define BK     64               // halves per stage-k = 128 bytes per row
#define STAGES 4
#define KT     (DIN / BK)       // 64

#define A_BYTES     (BM * 128)              // 32768
#define B_BYTES     (BN * 128)              // 16384
#define STAGE_BYTES (A_BYTES + B_BYTES)     // 49152
#define SMEM_DATA0  1024
#define SMEM_TOTAL  (SMEM_DATA0 + STAGES * STAGE_BYTES)   // 197632

#define MBAR_FULL(s)  ((s) * 16)
#define MBAR_EMPTY(s) ((s) * 16 + 8)

#define NWARPS_C 8                       // compute warps (warp tile 64x64)
#define NTHREADS (NWARPS_C * 32 + 32)    // +1 producer warp = 288  (reg cap 227)

// ============================================================================
// Scratch: fp16 operands (dequantized W, converted X)
// ============================================================================
__device__ __half g_W16[(size_t)DOUT * DIN];   // 96 MB
__device__ __half g_X16[(size_t)MROWS * DIN];  // 32 MB

// ============================================================================
// PTX helpers
// ============================================================================
__device__ __forceinline__ uint32_t smem_u32(const void* p) {
    uint32_t a;
    asm("{ .reg .u64 t; cvta.to.shared.u64 t, %1; cvt.u32.u64 %0, t; }" : "=r"(a) : "l"(p));
    return a;
}
__device__ __forceinline__ uint32_t elect_one() {
    uint32_t p;
    asm volatile("{ .reg .pred p; elect.sync _|p, 0xFFFFFFFF; selp.b32 %0, 1, 0, p; }" : "=r"(p));
    return p;
}

#define MBAR_INIT(addr, cnt) \
    asm volatile("mbarrier.init.shared.b64 [%0], %1;" :: "r"(addr), "r"(cnt) : "memory")
#define MBAR_EXPECT_TX(addr, bytes) \
    asm volatile("mbarrier.arrive.expect_tx.shared.b64 _, [%0], %1;" :: "r"(addr), "r"(bytes) : "memory")
#define MBAR_ARRIVE(addr) \
    asm volatile("mbarrier.arrive.shared.b64 _, [%0];" :: "r"(addr) : "memory")

#define MBAR_WAIT(mbar_addr, phase_parity) do {                                         \
    uint32_t _mbar = (uint32_t)(mbar_addr);                                             \
    uint32_t _par  = (uint32_t)(phase_parity);                                          \
    uint32_t _done;                                                                     \
    asm volatile("{\n\t.reg .pred p;\n\t"                                               \
        "mbarrier.try_wait.parity.acquire.cta.shared::cta.b64 p, [%1], %2;\n\t"         \
        "selp.b32 %0, 1, 0, p;\n\t}"                                                    \
        : "=r"(_done) : "r"(_mbar), "r"(_par) : "memory");                              \
    if (!_done) {                                                                       \
        asm volatile("{\n\t.reg .pred P1;\n\t"                                          \
            "WAIT_LOOP_%=:\n\t"                                                         \
            "mbarrier.try_wait.parity.acquire.cta.shared::cta.b64 P1, [%0], %1, 0x989680;\n\t" \
            "@P1 bra.uni WAIT_DONE_%=;\n\t"                                             \
            "bra.uni WAIT_LOOP_%=;\n\t"                                                 \
            "WAIT_DONE_%=:\n\t}"                                                        \
            :: "r"(_mbar), "r"(_par) : "memory");                                       \
    }                                                                                   \
} while (0)

#define TMA_LOAD2D(smem, map, cx, cy, mbar)                                             \
    asm volatile("cp.async.bulk.tensor.2d.shared::cta.global.tile.mbarrier::complete_tx::bytes " \
                 "[%0], [%1, {%2, %3}], [%4];"                                          \
                 :: "r"(smem), "l"(map), "r"(cx), "r"(cy), "r"(mbar) : "memory")

#define LDSM_X4(r0, r1, r2, r3, addr)                                                   \
    asm volatile("ldmatrix.sync.aligned.m8n8.x4.shared.b16 {%0,%1,%2,%3}, [%4];"        \
                 : "=r"(r0), "=r"(r1), "=r"(r2), "=r"(r3) : "r"(addr))

__device__ __forceinline__ void mma_f16(float c[4], uint32_t a0, uint32_t a1, uint32_t a2,
                                        uint32_t a3, uint32_t b0, uint32_t b1) {
    asm volatile(
        "mma.sync.aligned.m16n8k16.row.col.f32.f16.f16.f32 "
        "{%0,%1,%2,%3}, {%4,%5,%6,%7}, {%8,%9}, {%0,%1,%2,%3};"
        : "+f"(c[0]), "+f"(c[1]), "+f"(c[2]), "+f"(c[3])
        : "r"(a0), "r"(a1), "r"(a2), "r"(a3), "r"(b0), "r"(b1));
}

// ============================================================================
// Merged prep: dequant W -> fp16, convert X -> fp16 (one launch; validated)
// ============================================================================
__device__ __forceinline__ uint32_t h2bits(float a, float b) {
    __half2 h = __floats2half2_rn(a, b);
    return *reinterpret_cast<uint32_t*>(&h);
}

#define W_BLOCKS ((DOUT * DIN / 8) / 256)   // 24576
#define X_BLOCKS ((MROWS * DIN / 8) / 256)  // 8192

__global__ void prep_kernel(const float4* __restrict__ x, const float4* __restrict__ peso,
                            const float* __restrict__ escala,
                            uint4* __restrict__ gX, uint4* __restrict__ gW) {
    const int bid = blockIdx.x;
    if (bid < W_BLOCKS) {
        int i = bid * 256 + threadIdx.x;
        int e   = i << 3;
        int row = e >> 12;            // / DIN
        int col = e & (DIN - 1);
        float s = __ldg(&escala[(row >> 7) * (DIN / 128) + (col >> 7)]);
        float4 v0 = peso[2 * i], v1 = peso[2 * i + 1];
        uint4 u;
        u.x = h2bits(v0.x * s, v0.y * s); u.y = h2bits(v0.z * s, v0.w * s);
        u.z = h2bits(v1.x * s, v1.y * s); u.w = h2bits(v1.z * s, v1.w * s);
        gW[i] = u;
    } else {
        int i = (bid - W_BLOCKS) * 256 + threadIdx.x;
        float4 v0 = x[2 * i], v1 = x[2 * i + 1];
        uint4 u;
        u.x = h2bits(v0.x, v0.y); u.y = h2bits(v0.z, v0.w);
        u.z = h2bits(v1.x, v1.y); u.w = h2bits(v1.z, v1.w);
        gX[i] = u;
    }
}

// ============================================================================
// GEMM: C[m,n] = sum_k X[m,k] * W[n,k]   (fp16 in, fp32 accum/out)
//   CTA 256x128, BK=64, 4-stage TMA ring, occ 1.
//   8 compute warps (4M x 2N grid, warp tile 64x64) + 1 TMA producer warp.
//   FLAT software pipeline: fragments double-buffered ACROSS stage boundaries.
//   At ks=3 we wait FULL(next) and prefetch next stage's ks=0 fragments before
//   issuing ks=3's MMAs -> boundary wait + LDSM chain hides under ~256 issue
//   cycles of MMAs. EMPTY arrive stays after the last MMA (safe protocol).
// ============================================================================
__global__ void __launch_bounds__(NTHREADS, 1)
gemm_f16_kernel(const __grid_constant__ CUtensorMap tmA,
                const __grid_constant__ CUtensorMap tmB,
                float* __restrict__ out) {
    extern __shared__ char smem[];
    const uint32_t sb = smem_u32(smem);
    const int tid  = threadIdx.x;
    const int wid  = tid >> 5;
    const int lane = tid & 31;

    const int m0 = blockIdx.y * BM;
    const int n0 = blockIdx.x * BN;

    if (tid == 0) {
        for (int s = 0; s < STAGES; s++) {
            MBAR_INIT(sb + MBAR_FULL(s), 1);
            MBAR_INIT(sb + MBAR_EMPTY(s), NWARPS_C);
        }
    }
    __syncthreads();

    if (wid == NWARPS_C) {
        // ---------------- TMA producer warp ----------------
        if (elect_one()) {
            int s = 0, ph = 1;               // first STAGES empty-waits pass immediately
            for (int kt = 0; kt < KT; kt++) {
                MBAR_WAIT(sb + MBAR_EMPTY(s), ph);
                MBAR_EXPECT_TX(sb + MBAR_FULL(s), STAGE_BYTES);
                const uint32_t stg = sb + SMEM_DATA0 + s * STAGE_BYTES;
                TMA_LOAD2D(stg,           &tmA, kt * BK, m0, sb + MBAR_FULL(s));
                TMA_LOAD2D(stg + A_BYTES, &tmB, kt * BK, n0, sb + MBAR_FULL(s));
                if (s == STAGES - 1) { s = 0; ph ^= 1; } else { s++; }
            }
        }
        return;
    }

    // ---------------- compute warps: 4M x 2N grid, warp tile 64x64 ----------------
    const int warp_m = wid >> 1;         // 0..3 -> M offset 64*warp_m
    const int warp_n = wid & 1;          // 0..1 -> N offset 64*warp_n
    const int q  = lane >> 3;            // ldmatrix quad
    const int iq = lane & 7;

    const int a_rif  = ((q & 1) << 3) + iq;     // row within 16-row fragment
    const uint32_t a_csel = (uint32_t)(q >> 1); // 16B chunk select
    const int b_rif  = ((q >> 1) << 3) + iq;
    const uint32_t b_csel = (uint32_t)(q & 1);

    float c[4][8][4];
#pragma unroll
    for (int mf = 0; mf < 4; mf++)
#pragma unroll
        for (int nf = 0; nf < 8; nf++)
#pragma unroll
            for (int r = 0; r < 4; r++) c[mf][nf][r] = 0.0f;

    // row byte offsets (swizzle key is iq for every fragment row: rows % 8 == iq)
    uint32_t a_off[4], b_off[4];
#pragma unroll
    for (int mf = 0; mf < 4; mf++)
        a_off[mf] = (uint32_t)((warp_m * 64 + mf * 16 + a_rif) * 128);
#pragma unroll
    for (int p = 0; p < 4; p++)
        b_off[p] = (uint32_t)((warp_n * 64 + p * 16 + b_rif) * 128);

    uint32_t a[2][4][4], b[2][8][2];

    auto load_frags = [&](int ks, uint32_t (&af)[4][4], uint32_t (&bf)[8][2],
                          uint32_t As, uint32_t Bs) {
        const uint32_t xa = (((uint32_t)(2 * ks) + a_csel) ^ (uint32_t)iq) << 4;
        const uint32_t xb = (((uint32_t)(2 * ks) + b_csel) ^ (uint32_t)iq) << 4;
#pragma unroll
        for (int mf = 0; mf < 4; mf++)
            LDSM_X4(af[mf][0], af[mf][1], af[mf][2], af[mf][3], As + a_off[mf] + xa);
#pragma unroll
        for (int p = 0; p < 4; p++)
            LDSM_X4(bf[2 * p][0], bf[2 * p][1], bf[2 * p + 1][0], bf[2 * p + 1][1],
                    Bs + b_off[p] + xb);
    };

    int s = 0, ph = 0;
    MBAR_WAIT(sb + MBAR_FULL(0), 0);
    uint32_t As = sb + SMEM_DATA0;
    uint32_t Bs = As + A_BYTES;
    load_frags(0, a[0], b[0], As, Bs);     // prologue: stage 0, ks 0

    for (int kt = 0; kt < KT; kt++) {
        uint32_t nAs = As, nBs = Bs;
        int ns = s, nph = ph;
#pragma unroll
        for (int ks = 0; ks < 4; ks++) {       // 4 x k16 per stage, flat-pipelined
            if (ks < 3) {
                load_frags(ks + 1, a[(ks + 1) & 1], b[(ks + 1) & 1], As, Bs);
            } else if (kt + 1 < KT) {
                // cross-stage prefetch: wait next FULL, load its ks=0 frags
                ns  = (s == STAGES - 1) ? 0 : s + 1;
                nph = (s == STAGES - 1) ? (ph ^ 1) : ph;
                MBAR_WAIT(sb + MBAR_FULL(ns), nph);
                nAs = sb + SMEM_DATA0 + ns * STAGE_BYTES;
                nBs = nAs + A_BYTES;
                load_frags(0, a[0], b[0], nAs, nBs);   // (ks+1)&1 == 0
            }
            uint32_t (&af)[4][4] = a[ks & 1];
            uint32_t (&bf)[8][2] = b[ks & 1];
#pragma unroll
            for (int mf = 0; mf < 4; mf++)
#pragma unroll
                for (int nf = 0; nf < 8; nf++)
                    mma_f16(c[mf][nf], af[mf][0], af[mf][1], af[mf][2], af[mf][3],
                            bf[nf][0], bf[nf][1]);
        }
        // Safe point: all current-stage LDSM results consumed by mma.sync.
        __syncwarp();
        if (lane == 0) MBAR_ARRIVE(sb + MBAR_EMPTY(s));
        As = nAs; Bs = nBs; s = ns; ph = nph;
    }

    // ---------------- epilogue: direct float2 stores ----------------
    const int g   = lane >> 2;
    const int tig = lane & 3;
#pragma unroll
    for (int mf = 0; mf < 4; mf++) {
        const int m = m0 + warp_m * 64 + mf * 16 + g;
#pragma unroll
        for (int nf = 0; nf < 8; nf++) {
            const int n = n0 + warp_n * 64 + nf * 8 + tig * 2;
            *reinterpret_cast<float2*>(&out[(size_t)m * DOUT + n]) =
                make_float2(c[mf][nf][0], c[mf][nf][1]);
            *reinterpret_cast<float2*>(&out[(size_t)(m + 8) * DOUT + n]) =
                make_float2(c[mf][nf][2], c[mf][nf][3]);
        }
    }
}

// ============================================================================
// Host launch
// ============================================================================
typedef CUresult (*PFN_encodeTiled)(CUtensorMap*, CUtensorMapDataType, cuuint32_t, void*,
                                    const cuuint64_t*, const cuuint64_t*, const cuuint32_t*,
                                    const cuuint32_t*, CUtensorMapInterleave, CUtensorMapSwizzle,
                                    CUtensorMapL2promotion, CUtensorMapFloatOOBfill);

static PFN_encodeTiled get_encode_fn() {
    void* fn = nullptr;
#if CUDART_VERSION >= 12050
    cudaDriverEntryPointQueryResult qr;
    cudaGetDriverEntryPointByVersion("cuTensorMapEncodeTiled", &fn, 12000, cudaEnableDefault, &qr);
#else
    cudaGetDriverEntryPoint("cuTensorMapEncodeTiled", &fn, cudaEnableDefault);
#endif
    return (PFN_encodeTiled)fn;
}

static void encode_2d_f16(PFN_encodeTiled enc, CUtensorMap* tm, void* ptr,
                          uint64_t d0, uint64_t d1, uint32_t b0, uint32_t b1) {
    cuuint64_t dims[2]    = {d0, d1};
    cuuint64_t strides[1] = {d0 * sizeof(__half)};
    cuuint32_t box[2]     = {b0, b1};
    cuuint32_t es[2]      = {1, 1};
    enc(tm, CU_TENSOR_MAP_DATA_TYPE_FLOAT16, 2, ptr, dims, strides, box, es,
        CU_TENSOR_MAP_INTERLEAVE_NONE, CU_TENSOR_MAP_SWIZZLE_128B,
        CU_TENSOR_MAP_L2_PROMOTION_L2_128B, CU_TENSOR_MAP_FLOAT_OOB_FILL_NONE);
}

extern "C" void kernel_launch(void* const* d_in, const int* in_sizes, int n_in,
                              void* d_out, int out_size) {
    const float* x      = (const float*)d_in[0];
    const float* peso   = (const float*)d_in[1];
    const float* escala = (const float*)d_in[2];
    float* out          = (float*)d_out;

    __half *gX = nullptr, *gW = nullptr;
    cudaGetSymbolAddress((void**)&gX, g_X16);
    cudaGetSymbolAddress((void**)&gW, g_W16);

    prep_kernel<<<W_BLOCKS + X_BLOCKS, 256>>>((const float4*)x, (const float4*)peso, escala,
                                              (uint4*)gX, (uint4*)gW);

    PFN_encodeTiled enc = get_encode_fn();
    CUtensorMap tmA, tmB;
    encode_2d_f16(enc, &tmA, gX, DIN, MROWS, BK, BM);   // box 64x256
    encode_2d_f16(enc, &tmB, gW, DIN, DOUT,  BK, BN);   // box 64x128

    static bool attr_set = false;
    if (!attr_set) {
        cudaFuncSetAttribute(gemm_f16_kernel, cudaFuncAttributeMaxDynamicSharedMemorySize,
                             SMEM_TOTAL);
        attr_set = true;
    }

    dim3 grid(DOUT / BN, MROWS / BM);   // 96 x 16
    gemm_f16_kernel<<<grid, NTHREADS, SMEM_TOTAL>>>(tmA, tmB, out);
}

// round 11
// speedup vs baseline: 2.9835x; 2.9835x over previous
#include <cuda_runtime.h>
#include <cuda.h>
#include <cuda_fp16.h>
#include <cstdint>

// ============================================================================
// Problem constants   (R9 base; BK doubled, stages halved -> fewer boundaries)
// ============================================================================
#define DIN    4096
#define DOUT   12288
#define MROWS  4096

#define BM     256
#define BN     128
#define BK     128              // halves per stage-k (2 slabs of 64)
#define STAGES 2
#define KT     (DIN / BK)       // 32

#define A_SLAB      (BM * 128)              // 32768 (64 halves x 256 rows)
#define B_SLAB      (BN * 128)              // 16384
#define A_BYTES     (2 * A_SLAB)            // 65536
#define B_BYTES     (2 * B_SLAB)            // 32768
#define STAGE_BYTES (A_BYTES + B_BYTES)     // 98304
#define SMEM_DATA0  1024
#define SMEM_TOTAL  (SMEM_DATA0 + STAGES * STAGE_BYTES)   // 197632

#define MBAR_FULL(s)  ((s) * 16)
#define MBAR_EMPTY(s) ((s) * 16 + 8)

#define NWARPS_C 8                       // compute warps (warp tile 64x64)
#define NTHREADS (NWARPS_C * 32 + 32)    // +1 producer warp = 288  (reg cap 227)

// ============================================================================
// Scratch: fp16 operands (dequantized W, converted X)
// ============================================================================
__device__ __half g_W16[(size_t)DOUT * DIN];   // 96 MB
__device__ __half g_X16[(size_t)MROWS * DIN];  // 32 MB

// ============================================================================
// PTX helpers
// ============================================================================
__device__ __forceinline__ uint32_t smem_u32(const void* p) {
    uint32_t a;
    asm("{ .reg .u64 t; cvta.to.shared.u64 t, %1; cvt.u32.u64 %0, t; }" : "=r"(a) : "l"(p));
    return a;
}
__device__ __forceinline__ uint32_t elect_one() {
    uint32_t p;
    asm volatile("{ .reg .pred p; elect.sync _|p, 0xFFFFFFFF; selp.b32 %0, 1, 0, p; }" : "=r"(p));
    return p;
}

#define MBAR_INIT(addr, cnt) \
    asm volatile("mbarrier.init.shared.b64 [%0], %1;" :: "r"(addr), "r"(cnt) : "memory")
#define MBAR_EXPECT_TX(addr, bytes) \
    asm volatile("mbarrier.arrive.expect_tx.shared.b64 _, [%0], %1;" :: "r"(addr), "r"(bytes) : "memory")
#define MBAR_ARRIVE(addr) \
    asm volatile("mbarrier.arrive.shared.b64 _, [%0];" :: "r"(addr) : "memory")

#define MBAR_WAIT(mbar_addr, phase_parity) do {                                         \
    uint32_t _mbar = (uint32_t)(mbar_addr);                                             \
    uint32_t _par  = (uint32_t)(phase_parity);                                          \
    uint32_t _done;                                                                     \
    asm volatile("{\n\t.reg .pred p;\n\t"                                               \
        "mbarrier.try_wait.parity.acquire.cta.shared::cta.b64 p, [%1], %2;\n\t"         \
        "selp.b32 %0, 1, 0, p;\n\t}"                                                    \
        : "=r"(_done) : "r"(_mbar), "r"(_par) : "memory");                              \
    if (!_done) {                                                                       \
        asm volatile("{\n\t.reg .pred P1;\n\t"                                          \
            "WAIT_LOOP_%=:\n\t"                                                         \
            "mbarrier.try_wait.parity.acquire.cta.shared::cta.b64 P1, [%0], %1, 0x989680;\n\t" \
            "@P1 bra.uni WAIT_DONE_%=;\n\t"                                             \
            "bra.uni WAIT_LOOP_%=;\n\t"                                                 \
            "WAIT_DONE_%=:\n\t}"                                                        \
            :: "r"(_mbar), "r"(_par) : "memory");                                       \
    }                                                                                   \
} while (0)

#define TMA_LOAD2D(smem, map, cx, cy, mbar)                                             \
    asm volatile("cp.async.bulk.tensor.2d.shared::cta.global.tile.mbarrier::complete_tx::bytes " \
                 "[%0], [%1, {%2, %3}], [%4];"                                          \
                 :: "r"(smem), "l"(map), "r"(cx), "r"(cy), "r"(mbar) : "memory")

#define LDSM_X4(r0, r1, r2, r3, addr)                                                   \
    asm volatile("ldmatrix.sync.aligned.m8n8.x4.shared.b16 {%0,%1,%2,%3}, [%4];"        \
                 : "=r"(r0), "=r"(r1), "=r"(r2), "=r"(r3) : "r"(addr))

__device__ __forceinline__ void mma_f16(float c[4], uint32_t a0, uint32_t a1, uint32_t a2,
                                        uint32_t a3, uint32_t b0, uint32_t b1) {
    asm volatile(
        "mma.sync.aligned.m16n8k16.row.col.f32.f16.f16.f32 "
        "{%0,%1,%2,%3}, {%4,%5,%6,%7}, {%8,%9}, {%0,%1,%2,%3};"
        : "+f"(c[0]), "+f"(c[1]), "+f"(c[2]), "+f"(c[3])
        : "r"(a0), "r"(a1), "r"(a2), "r"(a3), "r"(b0), "r"(b1));
}

// ============================================================================
// Merged prep: dequant W -> fp16, convert X -> fp16 (one launch; validated)
// ============================================================================
__device__ __forceinline__ uint32_t h2bits(float a, float b) {
    __half2 h = __floats2half2_rn(a, b);
    return *reinterpret_cast<uint32_t*>(&h);
}

#define W_BLOCKS ((DOUT * DIN / 8) / 256)   // 24576
#define X_BLOCKS ((MROWS * DIN / 8) / 256)  // 8192

__global__ void prep_kernel(const float4* __restrict__ x, const float4* __restrict__ peso,
                            const float* __restrict__ escala,
                            uint4* __restrict__ gX, uint4* __restrict__ gW) {
    const int bid = blockIdx.x;
    if (bid < W_BLOCKS) {
        int i = bid * 256 + threadIdx.x;
        int e   = i << 3;
        int row = e >> 12;            // / DIN
        int col = e & (DIN - 1);
        float s = __ldg(&escala[(row >> 7) * (DIN / 128) + (col >> 7)]);
        float4 v0 = peso[2 * i], v1 = peso[2 * i + 1];
        uint4 u;
        u.x = h2bits(v0.x * s, v0.y * s); u.y = h2bits(v0.z * s, v0.w * s);
        u.z = h2bits(v1.x * s, v1.y * s); u.w = h2bits(v1.z * s, v1.w * s);
        gW[i] = u;
    } else {
        int i = (bid - W_BLOCKS) * 256 + threadIdx.x;
        float4 v0 = x[2 * i], v1 = x[2 * i + 1];
        uint4 u;
        u.x = h2bits(v0.x, v0.y); u.y = h2bits(v0.z, v0.w);
        u.z = h2bits(v1.x, v1.y); u.w = h2bits(v1.z, v1.w);
        gX[i] = u;
    }
}

// ============================================================================
// GEMM: C[m,n] = sum_k X[m,k] * W[n,k]   (fp16 in, fp32 accum/out)
//   CTA 256x128, BK=128 (2 slabs), 2-stage TMA ring (96KB/stage), occ 1.
//   8 compute warps (4M x 2N grid, warp tile 64x64) + 1 TMA producer warp.
//   Stage layout: [A slab0 32K][A slab1 32K][B slab0 16K][B slab1 16K].
//   R9 inner-loop protocol (the only one that schedules well): FULL wait at
//   kt-top only; straight-line unrolled 8 ks-steps with double-buffered
//   fragments; EMPTY arrive after the last MMA. Boundaries halve vs R9.
// ============================================================================
__global__ void __launch_bounds__(NTHREADS, 1)
gemm_f16_kernel(const __grid_constant__ CUtensorMap tmA,
                const __grid_constant__ CUtensorMap tmB,
                float* __restrict__ out) {
    extern __shared__ char smem[];
    const uint32_t sb = smem_u32(smem);
    const int tid  = threadIdx.x;
    const int wid  = tid >> 5;
    const int lane = tid & 31;

    const int m0 = blockIdx.y * BM;
    const int n0 = blockIdx.x * BN;

    if (tid == 0) {
        for (int s = 0; s < STAGES; s++) {
            MBAR_INIT(sb + MBAR_FULL(s), 1);
            MBAR_INIT(sb + MBAR_EMPTY(s), NWARPS_C);
        }
    }
    __syncthreads();

    if (wid == NWARPS_C) {
        // ---------------- TMA producer warp ----------------
        if (elect_one()) {
            int s = 0, ph = 1;               // first STAGES empty-waits pass immediately
            for (int kt = 0; kt < KT; kt++) {
                MBAR_WAIT(sb + MBAR_EMPTY(s), ph);
                MBAR_EXPECT_TX(sb + MBAR_FULL(s), STAGE_BYTES);
                const uint32_t stg = sb + SMEM_DATA0 + s * STAGE_BYTES;
                const int k0 = kt * BK;
                TMA_LOAD2D(stg,                       &tmA, k0,      m0, sb + MBAR_FULL(s));
                TMA_LOAD2D(stg + A_SLAB,              &tmA, k0 + 64, m0, sb + MBAR_FULL(s));
                TMA_LOAD2D(stg + A_BYTES,             &tmB, k0,      n0, sb + MBAR_FULL(s));
                TMA_LOAD2D(stg + A_BYTES + B_SLAB,    &tmB, k0 + 64, n0, sb + MBAR_FULL(s));
                if (s == STAGES - 1) { s = 0; ph ^= 1; } else { s++; }
            }
        }
        return;
    }

    // ---------------- compute warps: 4M x 2N grid, warp tile 64x64 ----------------
    const int warp_m = wid >> 1;         // 0..3 -> M offset 64*warp_m
    const int warp_n = wid & 1;          // 0..1 -> N offset 64*warp_n
    const int q  = lane >> 3;            // ldmatrix quad
    const int iq = lane & 7;

    const int a_rif  = ((q & 1) << 3) + iq;     // row within 16-row fragment
    const uint32_t a_csel = (uint32_t)(q >> 1); // 16B chunk select
    const int b_rif  = ((q >> 1) << 3) + iq;
    const uint32_t b_csel = (uint32_t)(q & 1);

    float c[4][8][4];
#pragma unroll
    for (int mf = 0; mf < 4; mf++)
#pragma unroll
        for (int nf = 0; nf < 8; nf++)
#pragma unroll
            for (int r = 0; r < 4; r++) c[mf][nf][r] = 0.0f;

    // row byte offsets (swizzle key is iq for every fragment row: rows % 8 == iq)
    uint32_t a_off[4], b_off[4];
#pragma unroll
    for (int mf = 0; mf < 4; mf++)
        a_off[mf] = (uint32_t)((warp_m * 64 + mf * 16 + a_rif) * 128);
#pragma unroll
    for (int p = 0; p < 4; p++)
        b_off[p] = (uint32_t)((warp_n * 64 + p * 16 + b_rif) * 128);

    uint32_t a[2][4][4], b[2][8][2];

    // ks in [0,8): 16B chunk index ch = 2*ks + csel in [0,16); slab = ch>>3.
    auto load_frags = [&](int ks, uint32_t (&af)[4][4], uint32_t (&bf)[8][2],
                          uint32_t As, uint32_t Bs) {
        const uint32_t cha = (uint32_t)(2 * ks) + a_csel;
        const uint32_t chb = (uint32_t)(2 * ks) + b_csel;
        const uint32_t baseA = As + (cha >> 3) * A_SLAB + (((cha & 7u) ^ (uint32_t)iq) << 4);
        const uint32_t baseB = Bs + (chb >> 3) * B_SLAB + (((chb & 7u) ^ (uint32_t)iq) << 4);
#pragma unroll
        for (int mf = 0; mf < 4; mf++)
            LDSM_X4(af[mf][0], af[mf][1], af[mf][2], af[mf][3], baseA + a_off[mf]);
#pragma unroll
        for (int p = 0; p < 4; p++)
            LDSM_X4(bf[2 * p][0], bf[2 * p][1], bf[2 * p + 1][0], bf[2 * p + 1][1],
                    baseB + b_off[p]);
    };

    int s = 0, ph = 0;
    for (int kt = 0; kt < KT; kt++) {
        MBAR_WAIT(sb + MBAR_FULL(s), ph);
        const uint32_t As = sb + SMEM_DATA0 + s * STAGE_BYTES;
        const uint32_t Bs = As + A_BYTES;

        load_frags(0, a[0], b[0], As, Bs);
#pragma unroll
        for (int ks = 0; ks < 8; ks++) {       // 8 x k16 per stage, double-buffered
            if (ks < 7) load_frags(ks + 1, a[(ks + 1) & 1], b[(ks + 1) & 1], As, Bs);
            uint32_t (&af)[4][4] = a[ks & 1];
            uint32_t (&bf)[8][2] = b[ks & 1];
#pragma unroll
            for (int mf = 0; mf < 4; mf++)
#pragma unroll
                for (int nf = 0; nf < 8; nf++)
                    mma_f16(c[mf][nf], af[mf][0], af[mf][1], af[mf][2], af[mf][3],
                            bf[nf][0], bf[nf][1]);
        }
        // Safe point: all this stage's LDSM results consumed by mma.sync.
        __syncwarp();
        if (lane == 0) MBAR_ARRIVE(sb + MBAR_EMPTY(s));
        if (s == STAGES - 1) { s = 0; ph ^= 1; } else { s++; }
    }

    // ---------------- epilogue: direct float2 stores ----------------
    const int g   = lane >> 2;
    const int tig = lane & 3;
#pragma unroll
    for (int mf = 0; mf < 4; mf++) {
        const int m = m0 + warp_m * 64 + mf * 16 + g;
#pragma unroll
        for (int nf = 0; nf < 8; nf++) {
            const int n = n0 + warp_n * 64 + nf * 8 + tig * 2;
            *reinterpret_cast<float2*>(&out[(size_t)m * DOUT + n]) =
                make_float2(c[mf][nf][0], c[mf][nf][1]);
            *reinterpret_cast<float2*>(&out[(size_t)(m + 8) * DOUT + n]) =
                make_float2(c[mf][nf][2], c[mf][nf][3]);
        }
    }
}

// ============================================================================
// Host launch
// ============================================================================
typedef CUresult (*PFN_encodeTiled)(CUtensorMap*, CUtensorMapDataType, cuuint32_t, void*,
                                    const cuuint64_t*, const cuuint64_t*, const cuuint32_t*,
                                    const cuuint32_t*, CUtensorMapInterleave, CUtensorMapSwizzle,
                                    CUtensorMapL2promotion, CUtensorMapFloatOOBfill);

static PFN_encodeTiled get_encode_fn() {
    void* fn = nullptr;
#if CUDART_VERSION >= 12050
    cudaDriverEntryPointQueryResult qr;
    cudaGetDriverEntryPointByVersion("cuTensorMapEncodeTiled", &fn, 12000, cudaEnableDefault, &qr);
#else
    cudaGetDriverEntryPoint("cuTensorMapEncodeTiled", &fn, cudaEnableDefault);
#endif
    return (PFN_encodeTiled)fn;
}

static void encode_2d_f16(PFN_encodeTiled enc, CUtensorMap* tm, void* ptr,
                          uint64_t d0, uint64_t d1, uint32_t b0, uint32_t b1) {
    cuuint64_t dims[2]    = {d0, d1};
    cuuint64_t strides[1] = {d0 * sizeof(__half)};
    cuuint32_t box[2]     = {b0, b1};
    cuuint32_t es[2]      = {1, 1};
    enc(tm, CU_TENSOR_MAP_DATA_TYPE_FLOAT16, 2, ptr, dims, strides, box, es,
        CU_TENSOR_MAP_INTERLEAVE_NONE, CU_TENSOR_MAP_SWIZZLE_128B,
        CU_TENSOR_MAP_L2_PROMOTION_L2_128B, CU_TENSOR_MAP_FLOAT_OOB_FILL_NONE);
}

extern "C" void kernel_launch(void* const* d_in, const int* in_sizes, int n_in,
                              void* d_out, int out_size) {
    const float* x      = (const float*)d_in[0];
    const float* peso   = (const float*)d_in[1];
    const float* escala = (const float*)d_in[2];
    float* out          = (float*)d_out;

    __half *gX = nullptr, *gW = nullptr;
    cudaGetSymbolAddress((void**)&gX, g_X16);
    cudaGetSymbolAddress((void**)&gW, g_W16);

    prep_kernel<<<W_BLOCKS + X_BLOCKS, 256>>>((const float4*)x, (const float4*)peso, escala,
                                              (uint4*)gX, (uint4*)gW);

    PFN_encodeTiled enc = get_encode_fn();
    CUtensorMap tmA, tmB;
    encode_2d_f16(enc, &tmA, gX, DIN, MROWS, 64, BM);   // box 64x256 (slab width)
    encode_2d_f16(enc, &tmB, gW, DIN, DOUT,  64, BN);   // box 64x128

    static bool attr_set = false;
    if (!attr_set) {
        cudaFuncSetAttribute(gemm_f16_kernel, cudaFuncAttributeMaxDynamicSharedMemorySize,
                             SMEM_TOTAL);
        attr_set = true;
    }

    dim3 grid(DOUT / BN, MROWS / BM);   // 96 x 16
    gemm_f16_kernel<<<grid, NTHREADS, SMEM_TOTAL>>>(tmA, tmB, out);
}

// round 12
// speedup vs baseline: 2.9842x; 1.0002x over previous
#include <cuda_runtime.h>
#include <cuda.h>
#include <cuda_fp16.h>
#include <cstdint>

// ============================================================================
// Problem constants   (R11 body, persistent-CTA schedule)
// ============================================================================
#define DIN    4096
#define DOUT   12288
#define MROWS  4096

#define BM     256
#define BN     128
#define BK     128              // halves per stage-k (2 slabs of 64)
#define STAGES 2
#define KT     (DIN / BK)       // 32

#define NX     (DOUT / BN)      // 96
#define NTILES (NX * (MROWS / BM))   // 1536

#define A_SLAB      (BM * 128)              // 32768
#define B_SLAB      (BN * 128)              // 16384
#define A_BYTES     (2 * A_SLAB)            // 65536
#define B_BYTES     (2 * B_SLAB)            // 32768
#define STAGE_BYTES (A_BYTES + B_BYTES)     // 98304
#define SMEM_DATA0  1024
#define SMEM_TOTAL  (SMEM_DATA0 + STAGES * STAGE_BYTES)   // 197632

#define MBAR_FULL(s)  ((s) * 16)
#define MBAR_EMPTY(s) ((s) * 16 + 8)

#define NWARPS_C 8                       // compute warps (warp tile 64x64)
#define NTHREADS (NWARPS_C * 32 + 32)    // +1 producer warp = 288  (reg cap 227)

// ============================================================================
// Scratch: fp16 operands (dequantized W, converted X)
// ============================================================================
__device__ __half g_W16[(size_t)DOUT * DIN];   // 96 MB
__device__ __half g_X16[(size_t)MROWS * DIN];  // 32 MB

// ============================================================================
// PTX helpers
// ============================================================================
__device__ __forceinline__ uint32_t smem_u32(const void* p) {
    uint32_t a;
    asm("{ .reg .u64 t; cvta.to.shared.u64 t, %1; cvt.u32.u64 %0, t; }" : "=r"(a) : "l"(p));
    return a;
}
__device__ __forceinline__ uint32_t elect_one() {
    uint32_t p;
    asm volatile("{ .reg .pred p; elect.sync _|p, 0xFFFFFFFF; selp.b32 %0, 1, 0, p; }" : "=r"(p));
    return p;
}

#define MBAR_INIT(addr, cnt) \
    asm volatile("mbarrier.init.shared.b64 [%0], %1;" :: "r"(addr), "r"(cnt) : "memory")
#define MBAR_EXPECT_TX(addr, bytes) \
    asm volatile("mbarrier.arrive.expect_tx.shared.b64 _, [%0], %1;" :: "r"(addr), "r"(bytes) : "memory")
#define MBAR_ARRIVE(addr) \
    asm volatile("mbarrier.arrive.shared.b64 _, [%0];" :: "r"(addr) : "memory")

#define MBAR_WAIT(mbar_addr, phase_parity) do {                                         \
    uint32_t _mbar = (uint32_t)(mbar_addr);                                             \
    uint32_t _par  = (uint32_t)(phase_parity);                                          \
    uint32_t _done;                                                                     \
    asm volatile("{\n\t.reg .pred p;\n\t"                                               \
        "mbarrier.try_wait.parity.acquire.cta.shared::cta.b64 p, [%1], %2;\n\t"         \
        "selp.b32 %0, 1, 0, p;\n\t}"                                                    \
        : "=r"(_done) : "r"(_mbar), "r"(_par) : "memory");                              \
    if (!_done) {                                                                       \
        asm volatile("{\n\t.reg .pred P1;\n\t"                                          \
            "WAIT_LOOP_%=:\n\t"                                                         \
            "mbarrier.try_wait.parity.acquire.cta.shared::cta.b64 P1, [%0], %1, 0x989680;\n\t" \
            "@P1 bra.uni WAIT_DONE_%=;\n\t"                                             \
            "bra.uni WAIT_LOOP_%=;\n\t"                                                 \
            "WAIT_DONE_%=:\n\t}"                                                        \
            :: "r"(_mbar), "r"(_par) : "memory");                                       \
    }                                                                                   \
} while (0)

#define TMA_LOAD2D(smem, map, cx, cy, mbar)                                             \
    asm volatile("cp.async.bulk.tensor.2d.shared::cta.global.tile.mbarrier::complete_tx::bytes " \
                 "[%0], [%1, {%2, %3}], [%4];"                                          \
                 :: "r"(smem), "l"(map), "r"(cx), "r"(cy), "r"(mbar) : "memory")

#define LDSM_X4(r0, r1, r2, r3, addr)                                                   \
    asm volatile("ldmatrix.sync.aligned.m8n8.x4.shared.b16 {%0,%1,%2,%3}, [%4];"        \
                 : "=r"(r0), "=r"(r1), "=r"(r2), "=r"(r3) : "r"(addr))

__device__ __forceinline__ void mma_f16(float c[4], uint32_t a0, uint32_t a1, uint32_t a2,
                                        uint32_t a3, uint32_t b0, uint32_t b1) {
    asm volatile(
        "mma.sync.aligned.m16n8k16.row.col.f32.f16.f16.f32 "
        "{%0,%1,%2,%3}, {%4,%5,%6,%7}, {%8,%9}, {%0,%1,%2,%3};"
        : "+f"(c[0]), "+f"(c[1]), "+f"(c[2]), "+f"(c[3])
        : "r"(a0), "r"(a1), "r"(a2), "r"(a3), "r"(b0), "r"(b1));
}

// ============================================================================
// Merged prep: dequant W -> fp16, convert X -> fp16 (one launch; validated)
// ============================================================================
__device__ __forceinline__ uint32_t h2bits(float a, float b) {
    __half2 h = __floats2half2_rn(a, b);
    return *reinterpret_cast<uint32_t*>(&h);
}

#define W_BLOCKS ((DOUT * DIN / 8) / 256)   // 24576
#define X_BLOCKS ((MROWS * DIN / 8) / 256)  // 8192

__global__ void prep_kernel(const float4* __restrict__ x, const float4* __restrict__ peso,
                            const float* __restrict__ escala,
                            uint4* __restrict__ gX, uint4* __restrict__ gW) {
    const int bid = blockIdx.x;
    if (bid < W_BLOCKS) {
        int i = bid * 256 + threadIdx.x;
        int e   = i << 3;
        int row = e >> 12;            // / DIN
        int col = e & (DIN - 1);
        float s = __ldg(&escala[(row >> 7) * (DIN / 128) + (col >> 7)]);
        float4 v0 = peso[2 * i], v1 = peso[2 * i + 1];
        uint4 u;
        u.x = h2bits(v0.x * s, v0.y * s); u.y = h2bits(v0.z * s, v0.w * s);
        u.z = h2bits(v1.x * s, v1.y * s); u.w = h2bits(v1.z * s, v1.w * s);
        gW[i] = u;
    } else {
        int i = (bid - W_BLOCKS) * 256 + threadIdx.x;
        float4 v0 = x[2 * i], v1 = x[2 * i + 1];
        uint4 u;
        u.x = h2bits(v0.x, v0.y); u.y = h2bits(v0.z, v0.w);
        u.z = h2bits(v1.x, v1.y); u.w = h2bits(v1.z, v1.w);
        gX[i] = u;
    }
}

// ============================================================================
// GEMM: C[m,n] = sum_k X[m,k] * W[n,k]   (fp16 in, fp32 accum/out)
//   PERSISTENT: gridDim.x = SM count; each CTA loops tiles t += gridDim.x.
//   Ring/phase state runs continuously across tiles (no tile-boundary sync):
//   producer prefetches the next tile's stages while consumers run the
//   epilogue -> prologue/epilogue off the critical path, no wave quantization.
//   Body identical to R11 (the only shape that schedules well).
// ============================================================================
__global__ void __launch_bounds__(NTHREADS, 1)
gemm_f16_kernel(const __grid_constant__ CUtensorMap tmA,
                const __grid_constant__ CUtensorMap tmB,
                float* __restrict__ out) {
    extern __shared__ char smem[];
    const uint32_t sb = smem_u32(smem);
    const int tid  = threadIdx.x;
    const int wid  = tid >> 5;
    const int lane = tid & 31;

    if (tid == 0) {
        for (int s = 0; s < STAGES; s++) {
            MBAR_INIT(sb + MBAR_FULL(s), 1);
            MBAR_INIT(sb + MBAR_EMPTY(s), NWARPS_C);
        }
    }
    __syncthreads();

    if (wid == NWARPS_C) {
        // ---------------- TMA producer warp (persistent) ----------------
        if (elect_one()) {
            int s = 0, ph = 1;               // first STAGES empty-waits pass immediately
            for (int t = blockIdx.x; t < NTILES; t += gridDim.x) {
                const int m0 = (t / NX) * BM;
                const int n0 = (t % NX) * BN;
                for (int kt = 0; kt < KT; kt++) {
                    MBAR_WAIT(sb + MBAR_EMPTY(s), ph);
                    MBAR_EXPECT_TX(sb + MBAR_FULL(s), STAGE_BYTES);
                    const uint32_t stg = sb + SMEM_DATA0 + s * STAGE_BYTES;
                    const int k0 = kt * BK;
                    TMA_LOAD2D(stg,                    &tmA, k0,      m0, sb + MBAR_FULL(s));
                    TMA_LOAD2D(stg + A_SLAB,           &tmA, k0 + 64, m0, sb + MBAR_FULL(s));
                    TMA_LOAD2D(stg + A_BYTES,          &tmB, k0,      n0, sb + MBAR_FULL(s));
                    TMA_LOAD2D(stg + A_BYTES + B_SLAB, &tmB, k0 + 64, n0, sb + MBAR_FULL(s));
                    if (s == STAGES - 1) { s = 0; ph ^= 1; } else { s++; }
                }
            }
        }
        return;
    }

    // ---------------- compute warps: 4M x 2N grid, warp tile 64x64 ----------------
    const int warp_m = wid >> 1;         // 0..3 -> M offset 64*warp_m
    const int warp_n = wid & 1;          // 0..1 -> N offset 64*warp_n
    const int q  = lane >> 3;            // ldmatrix quad
    const int iq = lane & 7;

    const int a_rif  = ((q & 1) << 3) + iq;     // row within 16-row fragment
    const uint32_t a_csel = (uint32_t)(q >> 1); // 16B chunk select
    const int b_rif  = ((q >> 1) << 3) + iq;
    const uint32_t b_csel = (uint32_t)(q & 1);

    // row byte offsets (tile-independent; swizzle key is iq for all rows)
    uint32_t a_off[4], b_off[4];
#pragma unroll
    for (int mf = 0; mf < 4; mf++)
        a_off[mf] = (uint32_t)((warp_m * 64 + mf * 16 + a_rif) * 128);
#pragma unroll
    for (int p = 0; p < 4; p++)
        b_off[p] = (uint32_t)((warp_n * 64 + p * 16 + b_rif) * 128);

    uint32_t a[2][4][4], b[2][8][2];

    auto load_frags = [&](int ks, uint32_t (&af)[4][4], uint32_t (&bf)[8][2],
                          uint32_t As, uint32_t Bs) {
        const uint32_t cha = (uint32_t)(2 * ks) + a_csel;
        const uint32_t chb = (uint32_t)(2 * ks) + b_csel;
        const uint32_t baseA = As + (cha >> 3) * A_SLAB + (((cha & 7u) ^ (uint32_t)iq) << 4);
        const uint32_t baseB = Bs + (chb >> 3) * B_SLAB + (((chb & 7u) ^ (uint32_t)iq) << 4);
#pragma unroll
        for (int mf = 0; mf < 4; mf++)
            LDSM_X4(af[mf][0], af[mf][1], af[mf][2], af[mf][3], baseA + a_off[mf]);
#pragma unroll
        for (int p = 0; p < 4; p++)
            LDSM_X4(bf[2 * p][0], bf[2 * p][1], bf[2 * p + 1][0], bf[2 * p + 1][1],
                    baseB + b_off[p]);
    };

    const int g   = lane >> 2;
    const int tig = lane & 3;

    int s = 0, ph = 0;                    // ring state persists across tiles
    for (int t = blockIdx.x; t < NTILES; t += gridDim.x) {
        const int m0 = (t / NX) * BM;
        const int n0 = (t % NX) * BN;

        float c[4][8][4];
#pragma unroll
        for (int mf = 0; mf < 4; mf++)
#pragma unroll
            for (int nf = 0; nf < 8; nf++)
#pragma unroll
                for (int r = 0; r < 4; r++) c[mf][nf][r] = 0.0f;

        for (int kt = 0; kt < KT; kt++) {
            MBAR_WAIT(sb + MBAR_FULL(s), ph);
            const uint32_t As = sb + SMEM_DATA0 + s * STAGE_BYTES;
            const uint32_t Bs = As + A_BYTES;

            load_frags(0, a[0], b[0], As, Bs);
#pragma unroll
            for (int ks = 0; ks < 8; ks++) {       // 8 x k16 per stage, double-buffered
                if (ks < 7) load_frags(ks + 1, a[(ks + 1) & 1], b[(ks + 1) & 1], As, Bs);
                uint32_t (&af)[4][4] = a[ks & 1];
                uint32_t (&bf)[8][2] = b[ks & 1];
#pragma unroll
                for (int mf = 0; mf < 4; mf++)
#pragma unroll
                    for (int nf = 0; nf < 8; nf++)
                        mma_f16(c[mf][nf], af[mf][0], af[mf][1], af[mf][2], af[mf][3],
                                bf[nf][0], bf[nf][1]);
            }
            // Safe point: stage's LDSM results all consumed by mma.sync.
            __syncwarp();
            if (lane == 0) MBAR_ARRIVE(sb + MBAR_EMPTY(s));
            if (s == STAGES - 1) { s = 0; ph ^= 1; } else { s++; }
        }

        // ---- epilogue (producer keeps prefetching next tile meanwhile) ----
#pragma unroll
        for (int mf = 0; mf < 4; mf++) {
            const int m = m0 + warp_m * 64 + mf * 16 + g;
#pragma unroll
            for (int nf = 0; nf < 8; nf++) {
                const int n = n0 + warp_n * 64 + nf * 8 + tig * 2;
                __stwt(reinterpret_cast<float2*>(&out[(size_t)m * DOUT + n]),
                       make_float2(c[mf][nf][0], c[mf][nf][1]));
                __stwt(reinterpret_cast<float2*>(&out[(size_t)(m + 8) * DOUT + n]),
                       make_float2(c[mf][nf][2], c[mf][nf][3]));
            }
        }
    }
}

// ============================================================================
// Host launch
// ============================================================================
typedef CUresult (*PFN_encodeTiled)(CUtensorMap*, CUtensorMapDataType, cuuint32_t, void*,
                                    const cuuint64_t*, const cuuint64_t*, const cuuint32_t*,
                                    const cuuint32_t*, CUtensorMapInterleave, CUtensorMapSwizzle,
                                    CUtensorMapL2promotion, CUtensorMapFloatOOBfill);

static PFN_encodeTiled get_encode_fn() {
    void* fn = nullptr;
#if CUDART_VERSION >= 12050
    cudaDriverEntryPointQueryResult qr;
    cudaGetDriverEntryPointByVersion("cuTensorMapEncodeTiled", &fn, 12000, cudaEnableDefault, &qr);
#else
    cudaGetDriverEntryPoint("cuTensorMapEncodeTiled", &fn, cudaEnableDefault);
#endif
    return (PFN_encodeTiled)fn;
}

static void encode_2d_f16(PFN_encodeTiled enc, CUtensorMap* tm, void* ptr,
                          uint64_t d0, uint64_t d1, uint32_t b0, uint32_t b1) {
    cuuint64_t dims[2]    = {d0, d1};
    cuuint64_t strides[1] = {d0 * sizeof(__half)};
    cuuint32_t box[2]     = {b0, b1};
    cuuint32_t es[2]      = {1, 1};
    enc(tm, CU_TENSOR_MAP_DATA_TYPE_FLOAT16, 2, ptr, dims, strides, box, es,
        CU_TENSOR_MAP_INTERLEAVE_NONE, CU_TENSOR_MAP_SWIZZLE_128B,
        CU_TENSOR_MAP_L2_PROMOTION_L2_128B, CU_TENSOR_MAP_FLOAT_OOB_FILL_NONE);
}

extern "C" void kernel_launch(void* const* d_in, const int* in_sizes, int n_in,
                              void* d_out, int out_size) {
    const float* x      = (const float*)d_in[0];
    const float* peso   = (const float*)d_in[1];
    const float* escala = (const float*)d_in[2];
    float* out          = (float*)d_out;

    __half *gX = nullptr, *gW = nullptr;
    cudaGetSymbolAddress((void**)&gX, g_X16);
    cudaGetSymbolAddress((void**)&gW, g_W16);

    prep_kernel<<<W_BLOCKS + X_BLOCKS, 256>>>((const float4*)x, (const float4*)peso, escala,
                                              (uint4*)gX, (uint4*)gW);

    PFN_encodeTiled enc = get_encode_fn();
    CUtensorMap tmA, tmB;
    encode_2d_f16(enc, &tmA, gX, DIN, MROWS, 64, BM);   // box 64x256 (slab width)
    encode_2d_f16(enc, &tmB, gW, DIN, DOUT,  64, BN);   // box 64x128

    static int nsm = 0;
    if (nsm == 0) {
        cudaDeviceGetAttribute(&nsm, cudaDevAttrMultiProcessorCount, 0);
        if (nsm <= 0) nsm = 148;
        cudaFuncSetAttribute(gemm_f16_kernel, cudaFuncAttributeMaxDynamicSharedMemorySize,
                             SMEM_TOTAL);
    }

    gemm_f16_kernel<<<nsm, NTHREADS, SMEM_TOTAL>>>(tmA, tmB, out);
}

// round 13
// speedup vs baseline: 3.1625x; 1.0598x over previous
#include <cuda_runtime.h>
#include <cuda.h>
#include <cuda_fp16.h>
#include <cstdint>

// ============================================================================
// Problem constants   (R11/R12 body; tail-balanced persistent schedule)
// ============================================================================
#define DIN    4096
#define DOUT   12288
#define MROWS  4096

#define BM     256
#define BN     128
#define BK     128              // halves per stage-k (2 slabs of 64)
#define STAGES 2
#define KT     (DIN / BK)       // 32

#define NX     (DOUT / BN)      // 96
#define NTILES (NX * (MROWS / BM))   // 1536

// Tail balancing: 1536 = 152*10 + 16. First 1520 tiles are full units
// (exact 10/CTA at grid 152); last 16 tiles are split into 8 K-chunks each.
#define FULL_UNITS  1520
#define REM_TILES   (NTILES - FULL_UNITS)        // 16
#define REM_CHUNKS  8                            // K chunks per remainder tile
#define REM_KT      (KT / REM_CHUNKS)            // 4 stages per chunk
#define TOTAL_UNITS (FULL_UNITS + REM_TILES * REM_CHUNKS)   // 1648

#define A_SLAB      (BM * 128)              // 32768
#define B_SLAB      (BN * 128)              // 16384
#define A_BYTES     (2 * A_SLAB)            // 65536
#define B_BYTES     (2 * B_SLAB)            // 32768
#define STAGE_BYTES (A_BYTES + B_BYTES)     // 98304
#define SMEM_DATA0  1024
#define SMEM_TOTAL  (SMEM_DATA0 + STAGES * STAGE_BYTES)   // 197632

#define MBAR_FULL(s)  ((s) * 16)
#define MBAR_EMPTY(s) ((s) * 16 + 8)

#define NWARPS_C 8                       // compute warps (warp tile 64x64)
#define NTHREADS (NWARPS_C * 32 + 32)    // +1 producer warp = 288

// ============================================================================
// Scratch: fp16 operands (dequantized W, converted X)
// ============================================================================
__device__ __half g_W16[(size_t)DOUT * DIN];   // 96 MB
__device__ __half g_X16[(size_t)MROWS * DIN];  // 32 MB

// ============================================================================
// PTX helpers
// ============================================================================
__device__ __forceinline__ uint32_t smem_u32(const void* p) {
    uint32_t a;
    asm("{ .reg .u64 t; cvta.to.shared.u64 t, %1; cvt.u32.u64 %0, t; }" : "=r"(a) : "l"(p));
    return a;
}
__device__ __forceinline__ uint32_t elect_one() {
    uint32_t p;
    asm volatile("{ .reg .pred p; elect.sync _|p, 0xFFFFFFFF; selp.b32 %0, 1, 0, p; }" : "=r"(p));
    return p;
}

#define MBAR_INIT(addr, cnt) \
    asm volatile("mbarrier.init.shared.b64 [%0], %1;" :: "r"(addr), "r"(cnt) : "memory")
#define MBAR_EXPECT_TX(addr, bytes) \
    asm volatile("mbarrier.arrive.expect_tx.shared.b64 _, [%0], %1;" :: "r"(addr), "r"(bytes) : "memory")
#define MBAR_ARRIVE(addr) \
    asm volatile("mbarrier.arrive.shared.b64 _, [%0];" :: "r"(addr) : "memory")

#define MBAR_WAIT(mbar_addr, phase_parity) do {                                         \
    uint32_t _mbar = (uint32_t)(mbar_addr);                                             \
    uint32_t _par  = (uint32_t)(phase_parity);                                          \
    uint32_t _done;                                                                     \
    asm volatile("{\n\t.reg .pred p;\n\t"                                               \
        "mbarrier.try_wait.parity.acquire.cta.shared::cta.b64 p, [%1], %2;\n\t"         \
        "selp.b32 %0, 1, 0, p;\n\t}"                                                    \
        : "=r"(_done) : "r"(_mbar), "r"(_par) : "memory");                              \
    if (!_done) {                                                                       \
        asm volatile("{\n\t.reg .pred P1;\n\t"                                          \
            "WAIT_LOOP_%=:\n\t"                                                         \
            "mbarrier.try_wait.parity.acquire.cta.shared::cta.b64 P1, [%0], %1, 0x989680;\n\t" \
            "@P1 bra.uni WAIT_DONE_%=;\n\t"                                             \
            "bra.uni WAIT_LOOP_%=;\n\t"                                                 \
            "WAIT_DONE_%=:\n\t}"                                                        \
            :: "r"(_mbar), "r"(_par) : "memory");                                       \
    }                                                                                   \
} while (0)

#define TMA_LOAD2D(smem, map, cx, cy, mbar)                                             \
    asm volatile("cp.async.bulk.tensor.2d.shared::cta.global.tile.mbarrier::complete_tx::bytes " \
                 "[%0], [%1, {%2, %3}], [%4];"                                          \
                 :: "r"(smem), "l"(map), "r"(cx), "r"(cy), "r"(mbar) : "memory")

#define LDSM_X4(r0, r1, r2, r3, addr)                                                   \
    asm volatile("ldmatrix.sync.aligned.m8n8.x4.shared.b16 {%0,%1,%2,%3}, [%4];"        \
                 : "=r"(r0), "=r"(r1), "=r"(r2), "=r"(r3) : "r"(addr))

__device__ __forceinline__ void mma_f16(float c[4], uint32_t a0, uint32_t a1, uint32_t a2,
                                        uint32_t a3, uint32_t b0, uint32_t b1) {
    asm volatile(
        "mma.sync.aligned.m16n8k16.row.col.f32.f16.f16.f32 "
        "{%0,%1,%2,%3}, {%4,%5,%6,%7}, {%8,%9}, {%0,%1,%2,%3};"
        : "+f"(c[0]), "+f"(c[1]), "+f"(c[2]), "+f"(c[3])
        : "r"(a0), "r"(a1), "r"(a2), "r"(a3), "r"(b0), "r"(b1));
}

// ============================================================================
// Merged prep: dequant W -> fp16, convert X -> fp16, zero split-K out region
// ============================================================================
__device__ __forceinline__ uint32_t h2bits(float a, float b) {
    __half2 h = __floats2half2_rn(a, b);
    return *reinterpret_cast<uint32_t*>(&h);
}

#define W_BLOCKS ((DOUT * DIN / 8) / 256)   // 24576
#define X_BLOCKS ((MROWS * DIN / 8) / 256)  // 8192
// remainder region: rows [3840,4096) x cols [10240,12288) = 2 MB -> uint4 fills
#define REM_ROW0  ((FULL_UNITS / NX) * BM)          // 3840  (FULL_UNITS/NX = 15)
#define REM_COL0  ((FULL_UNITS % NX) * BN)          // 10240 (FULL_UNITS%NX = 80)
#define REM_COLS  (DOUT - REM_COL0)                 // 2048
#define Z_ELEMS   (REM_TILES * BM * BN / 4 / 256)   // uint4 per... (computed below)
#define Z_BLOCKS  (((MROWS - REM_ROW0) * REM_COLS / 4) / 256)   // 512

__global__ void prep_kernel(const float4* __restrict__ x, const float4* __restrict__ peso,
                            const float* __restrict__ escala,
                            uint4* __restrict__ gX, uint4* __restrict__ gW,
                            float* __restrict__ out) {
    const int bid = blockIdx.x;
    if (bid < W_BLOCKS) {
        int i = bid * 256 + threadIdx.x;
        int e   = i << 3;
        int row = e >> 12;            // / DIN
        int col = e & (DIN - 1);
        float s = __ldg(&escala[(row >> 7) * (DIN / 128) + (col >> 7)]);
        float4 v0 = peso[2 * i], v1 = peso[2 * i + 1];
        uint4 u;
        u.x = h2bits(v0.x * s, v0.y * s); u.y = h2bits(v0.z * s, v0.w * s);
        u.z = h2bits(v1.x * s, v1.y * s); u.w = h2bits(v1.z * s, v1.w * s);
        gW[i] = u;
    } else if (bid < W_BLOCKS + X_BLOCKS) {
        int i = (bid - W_BLOCKS) * 256 + threadIdx.x;
        float4 v0 = x[2 * i], v1 = x[2 * i + 1];
        uint4 u;
        u.x = h2bits(v0.x, v0.y); u.y = h2bits(v0.z, v0.w);
        u.z = h2bits(v1.x, v1.y); u.w = h2bits(v1.z, v1.w);
        gX[i] = u;
    } else {
        // zero the split-K accumulation region of out
        int i = (bid - W_BLOCKS - X_BLOCKS) * 256 + threadIdx.x;   // float4 index
        int row = i / (REM_COLS / 4);
        int c4  = i % (REM_COLS / 4);
        float4 z = make_float4(0.f, 0.f, 0.f, 0.f);
        *reinterpret_cast<float4*>(&out[(size_t)(REM_ROW0 + row) * DOUT + REM_COL0 + c4 * 4]) = z;
    }
}

// ============================================================================
// GEMM: C[m,n] = sum_k X[m,k] * W[n,k]   (fp16 in, fp32 accum/out)
//   PERSISTENT, TAIL-BALANCED: 1520 full tiles (10/CTA at grid 152) then 128
//   split-K remainder units (16 tiles x 8 K-chunks, epilogue via atomicAdd
//   into pre-zeroed out region). Hot loop body identical to R11/R12.
// ============================================================================
__global__ void __launch_bounds__(NTHREADS, 1)
gemm_f16_kernel(const __grid_constant__ CUtensorMap tmA,
                const __grid_constant__ CUtensorMap tmB,
                float* __restrict__ out) {
    extern __shared__ char smem[];
    const uint32_t sb = smem_u32(smem);
    const int tid  = threadIdx.x;
    const int wid  = tid >> 5;
    const int lane = tid & 31;

    if (tid == 0) {
        for (int s = 0; s < STAGES; s++) {
            MBAR_INIT(sb + MBAR_FULL(s), 1);
            MBAR_INIT(sb + MBAR_EMPTY(s), NWARPS_C);
        }
    }
    __syncthreads();

    if (wid == NWARPS_C) {
        // ---------------- TMA producer warp (persistent) ----------------
        if (elect_one()) {
            int s = 0, ph = 1;
            for (int u = blockIdx.x; u < TOTAL_UNITS; u += gridDim.x) {
                int t, kt0, kt1;
                if (u < FULL_UNITS) { t = u; kt0 = 0; kt1 = KT; }
                else {
                    int r = u - FULL_UNITS;
                    t = FULL_UNITS + (r >> 3);
                    kt0 = (r & 7) * REM_KT; kt1 = kt0 + REM_KT;
                }
                const int m0 = (t / NX) * BM;
                const int n0 = (t % NX) * BN;
                for (int kt = kt0; kt < kt1; kt++) {
                    MBAR_WAIT(sb + MBAR_EMPTY(s), ph);
                    MBAR_EXPECT_TX(sb + MBAR_FULL(s), STAGE_BYTES);
                    const uint32_t stg = sb + SMEM_DATA0 + s * STAGE_BYTES;
                    const int k0 = kt * BK;
                    TMA_LOAD2D(stg,                    &tmA, k0,      m0, sb + MBAR_FULL(s));
                    TMA_LOAD2D(stg + A_SLAB,           &tmA, k0 + 64, m0, sb + MBAR_FULL(s));
                    TMA_LOAD2D(stg + A_BYTES,          &tmB, k0,      n0, sb + MBAR_FULL(s));
                    TMA_LOAD2D(stg + A_BYTES + B_SLAB, &tmB, k0 + 64, n0, sb + MBAR_FULL(s));
                    if (s == STAGES - 1) { s = 0; ph ^= 1; } else { s++; }
                }
            }
        }
        return;
    }

    // ---------------- compute warps: 4M x 2N grid, warp tile 64x64 ----------------
    const int warp_m = wid >> 1;
    const int warp_n = wid & 1;
    const int q  = lane >> 3;
    const int iq = lane & 7;

    const int a_rif  = ((q & 1) << 3) + iq;
    const uint32_t a_csel = (uint32_t)(q >> 1);
    const int b_rif  = ((q >> 1) << 3) + iq;
    const uint32_t b_csel = (uint32_t)(q & 1);

    uint32_t a_off[4], b_off[4];
#pragma unroll
    for (int mf = 0; mf < 4; mf++)
        a_off[mf] = (uint32_t)((warp_m * 64 + mf * 16 + a_rif) * 128);
#pragma unroll
    for (int p = 0; p < 4; p++)
        b_off[p] = (uint32_t)((warp_n * 64 + p * 16 + b_rif) * 128);

    uint32_t a[2][4][4], b[2][8][2];

    auto load_frags = [&](int ks, uint32_t (&af)[4][4], uint32_t (&bf)[8][2],
                          uint32_t As, uint32_t Bs) {
        const uint32_t cha = (uint32_t)(2 * ks) + a_csel;
        const uint32_t chb = (uint32_t)(2 * ks) + b_csel;
        const uint32_t baseA = As + (cha >> 3) * A_SLAB + (((cha & 7u) ^ (uint32_t)iq) << 4);
        const uint32_t baseB = Bs + (chb >> 3) * B_SLAB + (((chb & 7u) ^ (uint32_t)iq) << 4);
#pragma unroll
        for (int mf = 0; mf < 4; mf++)
            LDSM_X4(af[mf][0], af[mf][1], af[mf][2], af[mf][3], baseA + a_off[mf]);
#pragma unroll
        for (int p = 0; p < 4; p++)
            LDSM_X4(bf[2 * p][0], bf[2 * p][1], bf[2 * p + 1][0], bf[2 * p + 1][1],
                    baseB + b_off[p]);
    };

    const int g   = lane >> 2;
    const int tig = lane & 3;

    int s = 0, ph = 0;                    // ring state persists across units
    for (int u = blockIdx.x; u < TOTAL_UNITS; u += gridDim.x) {
        int t, kt0, kt1;
        const bool full = (u < FULL_UNITS);
        if (full) { t = u; kt0 = 0; kt1 = KT; }
        else {
            int r = u - FULL_UNITS;
            t = FULL_UNITS + (r >> 3);
            kt0 = (r & 7) * REM_KT; kt1 = kt0 + REM_KT;
        }
        const int m0 = (t / NX) * BM;
        const int n0 = (t % NX) * BN;

        float c[4][8][4];
#pragma unroll
        for (int mf = 0; mf < 4; mf++)
#pragma unroll
            for (int nf = 0; nf < 8; nf++)
#pragma unroll
                for (int r = 0; r < 4; r++) c[mf][nf][r] = 0.0f;

        for (int kt = kt0; kt < kt1; kt++) {
            MBAR_WAIT(sb + MBAR_FULL(s), ph);
            const uint32_t As = sb + SMEM_DATA0 + s * STAGE_BYTES;
            const uint32_t Bs = As + A_BYTES;

            load_frags(0, a[0], b[0], As, Bs);
#pragma unroll
            for (int ks = 0; ks < 8; ks++) {
                if (ks < 7) load_frags(ks + 1, a[(ks + 1) & 1], b[(ks + 1) & 1], As, Bs);
                uint32_t (&af)[4][4] = a[ks & 1];
                uint32_t (&bf)[8][2] = b[ks & 1];
#pragma unroll
                for (int mf = 0; mf < 4; mf++)
#pragma unroll
                    for (int nf = 0; nf < 8; nf++)
                        mma_f16(c[mf][nf], af[mf][0], af[mf][1], af[mf][2], af[mf][3],
                                bf[nf][0], bf[nf][1]);
            }
            __syncwarp();
            if (lane == 0) MBAR_ARRIVE(sb + MBAR_EMPTY(s));
            if (s == STAGES - 1) { s = 0; ph ^= 1; } else { s++; }
        }

        // ---- epilogue ----
        if (full) {
#pragma unroll
            for (int mf = 0; mf < 4; mf++) {
                const int m = m0 + warp_m * 64 + mf * 16 + g;
#pragma unroll
                for (int nf = 0; nf < 8; nf++) {
                    const int n = n0 + warp_n * 64 + nf * 8 + tig * 2;
                    __stwt(reinterpret_cast<float2*>(&out[(size_t)m * DOUT + n]),
                           make_float2(c[mf][nf][0], c[mf][nf][1]));
                    __stwt(reinterpret_cast<float2*>(&out[(size_t)(m + 8) * DOUT + n]),
                           make_float2(c[mf][nf][2], c[mf][nf][3]));
                }
            }
        } else {
            // split-K partial: accumulate into pre-zeroed region
#pragma unroll
            for (int mf = 0; mf < 4; mf++) {
                const int m = m0 + warp_m * 64 + mf * 16 + g;
#pragma unroll
                for (int nf = 0; nf < 8; nf++) {
                    const int n = n0 + warp_n * 64 + nf * 8 + tig * 2;
                    atomicAdd(&out[(size_t)m * DOUT + n],           c[mf][nf][0]);
                    atomicAdd(&out[(size_t)m * DOUT + n + 1],       c[mf][nf][1]);
                    atomicAdd(&out[(size_t)(m + 8) * DOUT + n],     c[mf][nf][2]);
                    atomicAdd(&out[(size_t)(m + 8) * DOUT + n + 1], c[mf][nf][3]);
                }
            }
        }
    }
}

// ============================================================================
// Host launch
// ============================================================================
typedef CUresult (*PFN_encodeTiled)(CUtensorMap*, CUtensorMapDataType, cuuint32_t, void*,
                                    const cuuint64_t*, const cuuint64_t*, const cuuint32_t*,
                                    const cuuint32_t*, CUtensorMapInterleave, CUtensorMapSwizzle,
                                    CUtensorMapL2promotion, CUtensorMapFloatOOBfill);

static PFN_encodeTiled get_encode_fn() {
    void* fn = nullptr;
#if CUDART_VERSION >= 12050
    cudaDriverEntryPointQueryResult qr;
    cudaGetDriverEntryPointByVersion("cuTensorMapEncodeTiled", &fn, 12000, cudaEnableDefault, &qr);
#else
    cudaGetDriverEntryPoint("cuTensorMapEncodeTiled", &fn, cudaEnableDefault);
#endif
    return (PFN_encodeTiled)fn;
}

static void encode_2d_f16(PFN_encodeTiled enc, CUtensorMap* tm, void* ptr,
                          uint64_t d0, uint64_t d1, uint32_t b0, uint32_t b1) {
    cuuint64_t dims[2]    = {d0, d1};
    cuuint64_t strides[1] = {d0 * sizeof(__half)};
    cuuint32_t box[2]     = {b0, b1};
    cuuint32_t es[2]      = {1, 1};
    enc(tm, CU_TENSOR_MAP_DATA_TYPE_FLOAT16, 2, ptr, dims, strides, box, es,
        CU_TENSOR_MAP_INTERLEAVE_NONE, CU_TENSOR_MAP_SWIZZLE_128B,
        CU_TENSOR_MAP_L2_PROMOTION_L2_128B, CU_TENSOR_MAP_FLOAT_OOB_FILL_NONE);
}

extern "C" void kernel_launch(void* const* d_in, const int* in_sizes, int n_in,
                              void* d_out, int out_size) {
    const float* x      = (const float*)d_in[0];
    const float* peso   = (const float*)d_in[1];
    const float* escala = (const float*)d_in[2];
    float* out          = (float*)d_out;

    __half *gX = nullptr, *gW = nullptr;
    cudaGetSymbolAddress((void**)&gX, g_X16);
    cudaGetSymbolAddress((void**)&gW, g_W16);

    prep_kernel<<<W_BLOCKS + X_BLOCKS + Z_BLOCKS, 256>>>(
        (const float4*)x, (const float4*)peso, escala, (uint4*)gX, (uint4*)gW, out);

    PFN_encodeTiled enc = get_encode_fn();
    CUtensorMap tmA, tmB;
    encode_2d_f16(enc, &tmA, gX, DIN, MROWS, 64, BM);   // box 64x256 (slab width)
    encode_2d_f16(enc, &tmB, gW, DIN, DOUT,  64, BN);   // box 64x128

    static int nsm = 0;
    if (nsm == 0) {
        cudaDeviceGetAttribute(&nsm, cudaDevAttrMultiProcessorCount, 0);
        if (nsm <= 0) nsm = 152;
        cudaFuncSetAttribute(gemm_f16_kernel, cudaFuncAttributeMaxDynamicSharedMemorySize,
                             SMEM_TOTAL);
    }

    gemm_f16_kernel<<<nsm, NTHREADS, SMEM_TOTAL>>>(tmA, tmB, out);
}

// round 14
// speedup vs baseline: 3.2699x; 1.0339x over previous
#include <cuda_runtime.h>
#include <cuda.h>
#include <cuda_fp16.h>
#include <cstdint>

// ============================================================================
// Problem constants — producer-less 12-warp cooperative pipeline
// ============================================================================
#define DIN    4096
#define DOUT   12288
#define MROWS  4096

#define BM     256              // 4 warp-rows x 64
#define BN     192              // 3 warp-cols x 64
#define BK     128              // halves per stage (2 slabs of 64)
#define KT     32               // DIN / BK

#define NMT    16               // MROWS/BM
#define NNT    64               // DOUT/BN
#define NTILES 1024             // column-major: t -> (m = t & 15, n = t >> 4)

#define GRID        152
#define FULL_UNITS  912         // 152 * 6  -> exactly 6 full tiles per CTA
#define REM_TILES   112         // tiles 912..1023  (cols >= 10944)
#define REM_CHUNKS  8
#define REM_KT      4           // KT / REM_CHUNKS
#define TOTAL_UNITS (FULL_UNITS + REM_TILES * REM_CHUNKS)   // 1808

#define A_SLAB      (BM * 128)              // 32768
#define B_SLAB      (BN * 128)              // 24576
#define A_BYTES     (2 * A_SLAB)            // 65536
#define B_BYTES     (2 * B_SLAB)            // 49152
#define STAGE_BYTES (A_BYTES + B_BYTES)     // 114688
#define SMEM_DATA0  1024
#define SMEM_TOTAL  (SMEM_DATA0 + 2 * STAGE_BYTES)   // 230400 (fits: R8 launched this)

#define MBAR_FULL(s)  ((s) * 16)            // two FULL barriers at sb+0, sb+16
#define CTRL_CNT      64                    // 2 ints: per-slot arrive counters
#define CTRL_GNEXT    80                    // 2 ints: per-slot next stage seq

#define NWARPS   12
#define NTHREADS 384                        // reg cap 170; body compiles at 168

// ============================================================================
// Scratch: fp16 operands (dequantized W, converted X)
// ============================================================================
__device__ __half g_W16[(size_t)DOUT * DIN];   // 96 MB
__device__ __half g_X16[(size_t)MROWS * DIN];  // 32 MB

// ============================================================================
// PTX helpers
// ============================================================================
__device__ __forceinline__ uint32_t smem_u32(const void* p) {
    uint32_t a;
    asm("{ .reg .u64 t; cvta.to.shared.u64 t, %1; cvt.u32.u64 %0, t; }" : "=r"(a) : "l"(p));
    return a;
}

#define MBAR_INIT(addr, cnt) \
    asm volatile("mbarrier.init.shared.b64 [%0], %1;" :: "r"(addr), "r"(cnt) : "memory")
#define MBAR_EXPECT_TX(addr, bytes) \
    asm volatile("mbarrier.arrive.expect_tx.shared.b64 _, [%0], %1;" :: "r"(addr), "r"(bytes) : "memory")

#define MBAR_WAIT(mbar_addr, phase_parity) do {                                         \
    uint32_t _mbar = (uint32_t)(mbar_addr);                                             \
    uint32_t _par  = (uint32_t)(phase_parity);                                          \
    uint32_t _done;                                                                     \
    asm volatile("{\n\t.reg .pred p;\n\t"                                               \
        "mbarrier.try_wait.parity.acquire.cta.shared::cta.b64 p, [%1], %2;\n\t"         \
        "selp.b32 %0, 1, 0, p;\n\t}"                                                    \
        : "=r"(_done) : "r"(_mbar), "r"(_par) : "memory");                              \
    if (!_done) {                                                                       \
        asm volatile("{\n\t.reg .pred P1;\n\t"                                          \
            "WAIT_LOOP_%=:\n\t"                                                         \
            "mbarrier.try_wait.parity.acquire.cta.shared::cta.b64 P1, [%0], %1, 0x989680;\n\t" \
            "@P1 bra.uni WAIT_DONE_%=;\n\t"                                             \
            "bra.uni WAIT_LOOP_%=;\n\t"                                                 \
            "WAIT_DONE_%=:\n\t}"                                                        \
            :: "r"(_mbar), "r"(_par) : "memory");                                       \
    }                                                                                   \
} while (0)

#define TMA_LOAD2D(smem, map, cx, cy, mbar)                                             \
    asm volatile("cp.async.bulk.tensor.2d.shared::cta.global.tile.mbarrier::complete_tx::bytes " \
                 "[%0], [%1, {%2, %3}], [%4];"                                          \
                 :: "r"(smem), "l"(map), "r"(cx), "r"(cy), "r"(mbar) : "memory")

#define LDSM_X4(r0, r1, r2, r3, addr)                                                   \
    asm volatile("ldmatrix.sync.aligned.m8n8.x4.shared.b16 {%0,%1,%2,%3}, [%4];"        \
                 : "=r"(r0), "=r"(r1), "=r"(r2), "=r"(r3) : "r"(addr))

__device__ __forceinline__ void mma_f16(float c[4], uint32_t a0, uint32_t a1, uint32_t a2,
                                        uint32_t a3, uint32_t b0, uint32_t b1) {
    asm volatile(
        "mma.sync.aligned.m16n8k16.row.col.f32.f16.f16.f32 "
        "{%0,%1,%2,%3}, {%4,%5,%6,%7}, {%8,%9}, {%0,%1,%2,%3};"
        : "+f"(c[0]), "+f"(c[1]), "+f"(c[2]), "+f"(c[3])
        : "r"(a0), "r"(a1), "r"(a2), "r"(a3), "r"(b0), "r"(b1));
}

// ============================================================================
// Merged prep: dequant W -> fp16, convert X -> fp16, zero split-K out strip
// ============================================================================
__device__ __forceinline__ uint32_t h2bits(float a, float b) {
    __half2 h = __floats2half2_rn(a, b);
    return *reinterpret_cast<uint32_t*>(&h);
}

#define W_BLOCKS ((DOUT * DIN / 8) / 256)   // 24576
#define X_BLOCKS ((MROWS * DIN / 8) / 256)  // 8192
#define REM_COL0  10944                     // (912 >> 4) * 192
#define REM_COLS  1344                      // DOUT - REM_COL0
#define Z_BLOCKS  ((MROWS * REM_COLS / 4) / 256)   // 5376

__global__ void prep_kernel(const float4* __restrict__ x, const float4* __restrict__ peso,
                            const float* __restrict__ escala,
                            uint4* __restrict__ gX, uint4* __restrict__ gW,
                            float* __restrict__ out) {
    const int bid = blockIdx.x;
    if (bid < W_BLOCKS) {
        int i = bid * 256 + threadIdx.x;
        int e   = i << 3;
        int row = e >> 12;            // / DIN
        int col = e & (DIN - 1);
        float s = __ldg(&escala[(row >> 7) * (DIN / 128) + (col >> 7)]);
        float4 v0 = peso[2 * i], v1 = peso[2 * i + 1];
        uint4 u;
        u.x = h2bits(v0.x * s, v0.y * s); u.y = h2bits(v0.z * s, v0.w * s);
        u.z = h2bits(v1.x * s, v1.y * s); u.w = h2bits(v1.z * s, v1.w * s);
        gW[i] = u;
    } else if (bid < W_BLOCKS + X_BLOCKS) {
        int i = (bid - W_BLOCKS) * 256 + threadIdx.x;
        float4 v0 = x[2 * i], v1 = x[2 * i + 1];
        uint4 u;
        u.x = h2bits(v0.x, v0.y); u.y = h2bits(v0.z, v0.w);
        u.z = h2bits(v1.x, v1.y); u.w = h2bits(v1.z, v1.w);
        gX[i] = u;
    } else {
        // zero the split-K strip: all rows, cols [10944, 12288)
        int i = (bid - W_BLOCKS - X_BLOCKS) * 256 + threadIdx.x;   // float4 index
        int row = i / (REM_COLS / 4);
        int c4  = i % (REM_COLS / 4);
        *reinterpret_cast<float4*>(&out[(size_t)row * DOUT + REM_COL0 + c4 * 4]) =
            make_float4(0.f, 0.f, 0.f, 0.f);
    }
}

// ============================================================================
// GEMM: C[m,n] = sum_k X[m,k] * W[n,k]   (fp16 in, fp32 accum/out)
//   Producer-less 12-warp pipeline, CTA 256x192, 2-stage ring (112KB/stage).
//   Stage load is triggered by the 12th warp to finish a slot (atomic counter);
//   the trigger thread issues expect_tx + 4 TMAs itself. g_next handoff is
//   ordered by the arrive(release)/try_wait(acquire) chain on FULL.
//   Hot inner body identical to R11-R13 (only shape ptxas schedules well).
// ============================================================================
__global__ void __launch_bounds__(NTHREADS, 1)
gemm_f16_kernel(const __grid_constant__ CUtensorMap tmA,
                const __grid_constant__ CUtensorMap tmB,
                float* __restrict__ out) {
    extern __shared__ char smem[];
    const uint32_t sb = smem_u32(smem);
    int* scnt = reinterpret_cast<int*>(smem + CTRL_CNT);
    int* sgn  = reinterpret_cast<int*>(smem + CTRL_GNEXT);
    const int tid  = threadIdx.x;
    const int wid  = tid >> 5;
    const int lane = tid & 31;
    const int b    = blockIdx.x;

    // per-CTA stage-sequence length
    const int nch  = (b < 136) ? 6 : 5;          // chunk units per CTA (896 = 152*5+136)
    const int stot = 192 + 4 * nch;              // 6 full units * 32 stages + chunks

    // g -> (tile t, kt) for THIS CTA's stage sequence
    auto stage_coords = [&](int gq, int& t, int& kt) {
        if (gq < 192) {
            t  = b + 152 * (gq >> 5);            // full unit
            kt = gq & 31;
        } else {
            int h = gq - 192;
            int u = FULL_UNITS + b + 152 * (h >> 2);
            int r = u - FULL_UNITS;
            t  = FULL_UNITS + (r >> 3);
            kt = ((r & 7) << 2) + (h & 3);
        }
    };

    auto load_stage = [&](int gq, int slot) {
        int t, kt;
        stage_coords(gq, t, kt);
        const int m0 = (t & 15) * BM;
        const int n0 = (t >> 4) * BN;
        const int k0 = kt * BK;
        const uint32_t stg = sb + SMEM_DATA0 + slot * STAGE_BYTES;
        MBAR_EXPECT_TX(sb + MBAR_FULL(slot), STAGE_BYTES);
        TMA_LOAD2D(stg,                    &tmA, k0,      m0, sb + MBAR_FULL(slot));
        TMA_LOAD2D(stg + A_SLAB,           &tmA, k0 + 64, m0, sb + MBAR_FULL(slot));
        TMA_LOAD2D(stg + A_BYTES,          &tmB, k0,      n0, sb + MBAR_FULL(slot));
        TMA_LOAD2D(stg + A_BYTES + B_SLAB, &tmB, k0 + 64, n0, sb + MBAR_FULL(slot));
    };

    if (tid == 0) {
        MBAR_INIT(sb + MBAR_FULL(0), 1);
        MBAR_INIT(sb + MBAR_FULL(1), 1);
        scnt[0] = 0; scnt[1] = 0;
        sgn[0] = 2;  sgn[1] = 3;
    }
    __syncthreads();
    if (tid == 0) {                // prologue: fill both slots
        load_stage(0, 0);
        load_stage(1, 1);
    }

    // ---------------- compute warps: 4M x 3N grid, warp tile 64x64 ----------------
    const int warp_m = wid & 3;          // 0..3 -> M offset 64*warp_m
    const int warp_n = wid >> 2;         // 0..2 -> N offset 64*warp_n
    const int q  = lane >> 3;
    const int iq = lane & 7;

    const int a_rif  = ((q & 1) << 3) + iq;
    const uint32_t a_csel = (uint32_t)(q >> 1);
    const int b_rif  = ((q >> 1) << 3) + iq;
    const uint32_t b_csel = (uint32_t)(q & 1);

    uint32_t a_off[4], b_off[4];
#pragma unroll
    for (int mf = 0; mf < 4; mf++)
        a_off[mf] = (uint32_t)((warp_m * 64 + mf * 16 + a_rif) * 128);
#pragma unroll
    for (int p = 0; p < 4; p++)
        b_off[p] = (uint32_t)((warp_n * 64 + p * 16 + b_rif) * 128);

    uint32_t a[2][4][4], bfr[2][8][2];

    auto load_frags = [&](int ks, uint32_t (&af)[4][4], uint32_t (&bf)[8][2],
                          uint32_t As, uint32_t Bs) {
        const uint32_t cha = (uint32_t)(2 * ks) + a_csel;
        const uint32_t chb = (uint32_t)(2 * ks) + b_csel;
        const uint32_t baseA = As + (cha >> 3) * A_SLAB + (((cha & 7u) ^ (uint32_t)iq) << 4);
        const uint32_t baseB = Bs + (chb >> 3) * B_SLAB + (((chb & 7u) ^ (uint32_t)iq) << 4);
#pragma unroll
        for (int mf = 0; mf < 4; mf++)
            LDSM_X4(af[mf][0], af[mf][1], af[mf][2], af[mf][3], baseA + a_off[mf]);
#pragma unroll
        for (int p = 0; p < 4; p++)
            LDSM_X4(bf[2 * p][0], bf[2 * p][1], bf[2 * p + 1][0], bf[2 * p + 1][1],
                    baseB + b_off[p]);
    };

    const int g2l = lane >> 2;
    const int tig = lane & 3;

    int s = 0, ph = 0;                    // ring state persists across units
    for (int u = b; u < TOTAL_UNITS; u += GRID) {
        int t, kt0, kt1;
        const bool full = (u < FULL_UNITS);
        if (full) { t = u; kt0 = 0; kt1 = KT; }
        else {
            int r = u - FULL_UNITS;
            t = FULL_UNITS + (r >> 3);
            kt0 = (r & 7) * REM_KT; kt1 = kt0 + REM_KT;
        }
        const int m0 = (t & 15) * BM;
        const int n0 = (t >> 4) * BN;

        float c[4][8][4];
#pragma unroll
        for (int mf = 0; mf < 4; mf++)
#pragma unroll
            for (int nf = 0; nf < 8; nf++)
#pragma unroll
                for (int r = 0; r < 4; r++) c[mf][nf][r] = 0.0f;

        for (int kt = kt0; kt < kt1; kt++) {
            MBAR_WAIT(sb + MBAR_FULL(s), ph);
            const uint32_t As = sb + SMEM_DATA0 + s * STAGE_BYTES;
            const uint32_t Bs = As + A_BYTES;

            load_frags(0, a[0], bfr[0], As, Bs);
#pragma unroll
            for (int ks = 0; ks < 8; ks++) {
                if (ks < 7) load_frags(ks + 1, a[(ks + 1) & 1], bfr[(ks + 1) & 1], As, Bs);
                uint32_t (&af)[4][4] = a[ks & 1];
                uint32_t (&bf)[8][2] = bfr[ks & 1];
#pragma unroll
                for (int mf = 0; mf < 4; mf++)
#pragma unroll
                    for (int nf = 0; nf < 8; nf++)
                        mma_f16(c[mf][nf], af[mf][0], af[mf][1], af[mf][2], af[mf][3],
                                bf[nf][0], bf[nf][1]);
            }
            // Safe point: stage's LDSM results all consumed by mma.sync.
            __syncwarp();
            if (lane == 0) {
                int my = atomicAdd(&scnt[s], 1);
                if ((my % NWARPS) == NWARPS - 1) {     // last warp: reload this slot
                    int gq = sgn[s];
                    sgn[s] = gq + 2;
                    if (gq < stot) load_stage(gq, s);
                }
            }
            if (s == 1) { s = 0; ph ^= 1; } else { s = 1; }
        }

        // ---- epilogue ----
        if (full) {
#pragma unroll
            for (int mf = 0; mf < 4; mf++) {
                const int m = m0 + warp_m * 64 + mf * 16 + g2l;
#pragma unroll
                for (int nf = 0; nf < 8; nf++) {
                    const int n = n0 + warp_n * 64 + nf * 8 + tig * 2;
                    __stwt(reinterpret_cast<float2*>(&out[(size_t)m * DOUT + n]),
                           make_float2(c[mf][nf][0], c[mf][nf][1]));
                    __stwt(reinterpret_cast<float2*>(&out[(size_t)(m + 8) * DOUT + n]),
                           make_float2(c[mf][nf][2], c[mf][nf][3]));
                }
            }
        } else {
#pragma unroll
            for (int mf = 0; mf < 4; mf++) {
                const int m = m0 + warp_m * 64 + mf * 16 + g2l;
#pragma unroll
                for (int nf = 0; nf < 8; nf++) {
                    const int n = n0 + warp_n * 64 + nf * 8 + tig * 2;
                    atomicAdd(&out[(size_t)m * DOUT + n],           c[mf][nf][0]);
                    atomicAdd(&out[(size_t)m * DOUT + n + 1],       c[mf][nf][1]);
                    atomicAdd(&out[(size_t)(m + 8) * DOUT + n],     c[mf][nf][2]);
                    atomicAdd(&out[(size_t)(m + 8) * DOUT + n + 1], c[mf][nf][3]);
                }
            }
        }
    }
}

// ============================================================================
// Host launch
// ============================================================================
typedef CUresult (*PFN_encodeTiled)(CUtensorMap*, CUtensorMapDataType, cuuint32_t, void*,
                                    const cuuint64_t*, const cuuint64_t*, const cuuint32_t*,
                                    const cuuint32_t*, CUtensorMapInterleave, CUtensorMapSwizzle,
                                    CUtensorMapL2promotion, CUtensorMapFloatOOBfill);

static PFN_encodeTiled get_encode_fn() {
    void* fn = nullptr;
#if CUDART_VERSION >= 12050
    cudaDriverEntryPointQueryResult qr;
    cudaGetDriverEntryPointByVersion("cuTensorMapEncodeTiled", &fn, 12000, cudaEnableDefault, &qr);
#else
    cudaGetDriverEntryPoint("cuTensorMapEncodeTiled", &fn, cudaEnableDefault);
#endif
    return (PFN_encodeTiled)fn;
}

static void encode_2d_f16(PFN_encodeTiled enc, CUtensorMap* tm, void* ptr,
                          uint64_t d0, uint64_t d1, uint32_t b0, uint32_t b1) {
    cuuint64_t dims[2]    = {d0, d1};
    cuuint64_t strides[1] = {d0 * sizeof(__half)};
    cuuint32_t box[2]     = {b0, b1};
    cuuint32_t es[2]      = {1, 1};
    enc(tm, CU_TENSOR_MAP_DATA_TYPE_FLOAT16, 2, ptr, dims, strides, box, es,
        CU_TENSOR_MAP_INTERLEAVE_NONE, CU_TENSOR_MAP_SWIZZLE_128B,
        CU_TENSOR_MAP_L2_PROMOTION_L2_128B, CU_TENSOR_MAP_FLOAT_OOB_FILL_NONE);
}

extern "C" void kernel_launch(void* const* d_in, const int* in_sizes, int n_in,
                              void* d_out, int out_size) {
    const float* x      = (const float*)d_in[0];
    const float* peso   = (const float*)d_in[1];
    const float* escala = (const float*)d_in[2];
    float* out          = (float*)d_out;

    __half *gX = nullptr, *gW = nullptr;
    cudaGetSymbolAddress((void**)&gX, g_X16);
    cudaGetSymbolAddress((void**)&gW, g_W16);

    prep_kernel<<<W_BLOCKS + X_BLOCKS + Z_BLOCKS, 256>>>(
        (const float4*)x, (const float4*)peso, escala, (uint4*)gX, (uint4*)gW, out);

    PFN_encodeTiled enc = get_encode_fn();
    CUtensorMap tmA, tmB;
    encode_2d_f16(enc, &tmA, gX, DIN, MROWS, 64, BM);   // box 64x256 (slab width)
    encode_2d_f16(enc, &tmB, gW, DIN, DOUT,  64, BN);   // box 64x192

    static bool attr_set = false;
    if (!attr_set) {
        cudaFuncSetAttribute(gemm_f16_kernel, cudaFuncAttributeMaxDynamicSharedMemorySize,
                             SMEM_TOTAL);
        attr_set = true;
    }

    gemm_f16_kernel<<<GRID, NTHREADS, SMEM_TOTAL>>>(tmA, tmB, out);
}